// round 7
// baseline (speedup 1.0000x reference)
#include <cuda_runtime.h>

// PBKDF2-toy, serial single-warp register kernel. R7: pipe rebalance.
// One-warp bound: each pipe (fma/alu) takes 1 op per 2 cyc; alu-only ops are
// the binder. Old: 128 mix-LOP3 + 32 F-XOR = 160 alu -> 320 cyc/iter floor.
// New: F accumulated as packed halfword pairs -- pack = IMAD (fma pipe),
// xor = 1 LOP3 per pair -> forced-alu 144 (288), total 304 -> floor 304,
// balanced. STS spill of R6 reverted (store issue cost exceeded savings).
// Harness dtype shims: float32 out, dtype-sniffed in (proven R3).

__device__ __forceinline__ unsigned load_byte(const void* p, int i) {
    int v = ((const int*)p)[i];
    if ((unsigned)v <= 255u) return (unsigned)v;   // int32 input
    return (unsigned)(int)__int_as_float(v);       // float32 input
}

__global__ void __launch_bounds__(32, 1)
Model_62955630625117_kernel(const void* __restrict__ pw_in,
                            const void* __restrict__ salt_in,
                            float* __restrict__ out) {
    // All lanes uniform & convergent; lane 0 writes at the end.
    unsigned c[16];    // (pw[j]*31) & 255, loop-invariant
    unsigned r[32];    // hash state U (mix keeps bytes masked to 8 bits)
    unsigned Fp[16];   // packed xor accumulator: lo16 = F[i], hi16 = F[i+16]

    #pragma unroll
    for (int j = 0; j < 16; j++) {
        unsigned p = load_byte(pw_in, j);
        c[j] = (p * 31u) & 255u;
        r[j] = p;
    }
    #pragma unroll
    for (int j = 0; j < 16; j++) r[16 + j] = load_byte(salt_in, j);

    // First hmac message = salt(16) ++ block_num{0,0,0,1}: second absorb
    // touch on positions 0..3 only.
    r[0] = c[0];
    r[1] = c[1];
    r[2] = c[2];
    r[3] = (c[3] + 1u) & 255u;

    // U0 mix
    #pragma unroll
    for (int rd = 0; rd < 4; rd++) {
        #pragma unroll
        for (int i = 0; i < 32; i++)
            r[i] = (r[i] ^ (r[(i + 17) & 31] + r[(i + 11) & 31])) & 255u;
    }
    #pragma unroll
    for (int i = 0; i < 16; i++)
        Fp[i] = r[i] + (r[i + 16] << 16);          // IMAD pack, F init = U0

    // 999 chained iterations: U = hmac(pw, U); Fp ^= packed(U).
    // Absorb collapse: r[j] = c[j] + r[16+j] (9-bit OK, mix LOP3 re-masks),
    // r[16+j] = old r[j] (order-2 swap; even unroll -> pure renaming).
    #pragma unroll 4
    for (int it = 1; it < 1000; it++) {
        #pragma unroll
        for (int j = 0; j < 16; j++) {
            unsigned t = r[j];
            r[j] = c[j] + r[16 + j];
            r[16 + j] = t;
        }
        #pragma unroll
        for (int rd = 0; rd < 4; rd++) {
            #pragma unroll
            for (int i = 0; i < 32; i++)
                r[i] = (r[i] ^ (r[(i + 17) & 31] + r[(i + 11) & 31])) & 255u;
        }
        // F accumulation: 16x { IMAD pack (fma pipe) + XOR (alu pipe) }
        #pragma unroll
        for (int i = 0; i < 16; i++)
            Fp[i] ^= r[i] + (r[i + 16] << 16);     // r[i+16]*65536 + r[i] -> IMAD
    }

    if (threadIdx.x == 0) {
        #pragma unroll
        for (int i = 0; i < 16; i++) {
            out[i]      = (float)(Fp[i] & 0xFFFFu);
            out[i + 16] = (float)(Fp[i] >> 16);
        }
    }
}

extern "C" void kernel_launch(void* const* d_in, const int* in_sizes, int n_in,
                              void* d_out, int out_size) {
    const void* password = d_in[0];
    const void* salt     = (n_in >= 2) ? d_in[1] : (const void*)((const int*)d_in[0] + 16);
    float* out           = (float*)d_out;
    Model_62955630625117_kernel<<<1, 32>>>(password, salt, out);
}

// round 8
// speedup vs baseline: 1.0597x; 1.0597x over previous
#include <cuda_runtime.h>

// PBKDF2-toy, serial single-warp register kernel. R8: re-test the pipe-
// rebalance theory with codegen forced. One-warp model: alu pipe (LOP3-only
// ops) accepts 1 op/2cyc and is the binder (160 alu/iter -> 320 cyc floor).
// F accumulation moves half its ops to the fma pipe: pack pair (r[i],
// r[i+16]) with an inline-PTX mad.lo.u32 (guaranteed IMAD, fma pipe), xor
// the packed pair into Fp[i] (1 LOP3). alu/iter 160 -> 144, floor -> 288.
// R7 failed only because ptxas split the shift-add into SHF+IADD (+16 ops,
// measured 322 vs 295 issued/iter); mad.lo closes that hole.
// Pack+xor fused into mix round-4 steps 16..31 as latency fillers.
// Harness dtype shims: float32 out, dtype-sniffed in (proven R3).

__device__ __forceinline__ unsigned load_byte(const void* p, int i) {
    int v = ((const int*)p)[i];
    if ((unsigned)v <= 255u) return (unsigned)v;   // int32 input
    return (unsigned)(int)__int_as_float(v);       // float32 input
}

__device__ __forceinline__ unsigned pack16(unsigned hi, unsigned lo) {
    unsigned t;
    asm("mad.lo.u32 %0, %1, 65536, %2;" : "=r"(t) : "r"(hi), "r"(lo));
    return t;   // hi*65536 + lo, single IMAD on the fma pipe
}

__global__ void __launch_bounds__(32, 1)
Model_62955630625117_kernel(const void* __restrict__ pw_in,
                            const void* __restrict__ salt_in,
                            float* __restrict__ out) {
    // All lanes uniform & convergent; lane 0 writes at the end.
    unsigned c[16];    // (pw[j]*31) & 255, loop-invariant
    unsigned r[32];    // hash state U (mix LOP3 keeps bytes 8-bit)
    unsigned Fp[16];   // packed xor accumulator: lo16 = F[i], hi16 = F[i+16]

    #pragma unroll
    for (int j = 0; j < 16; j++) {
        unsigned p = load_byte(pw_in, j);
        c[j] = (p * 31u) & 255u;
        r[j] = p;
    }
    #pragma unroll
    for (int j = 0; j < 16; j++) r[16 + j] = load_byte(salt_in, j);

    // First hmac message = salt(16) ++ block_num{0,0,0,1}
    r[0] = c[0];
    r[1] = c[1];
    r[2] = c[2];
    r[3] = (c[3] + 1u) & 255u;

    // U0 mix
    #pragma unroll
    for (int rd = 0; rd < 4; rd++) {
        #pragma unroll
        for (int i = 0; i < 32; i++)
            r[i] = (r[i] ^ (r[(i + 17) & 31] + r[(i + 11) & 31])) & 255u;
    }
    #pragma unroll
    for (int i = 0; i < 16; i++)
        Fp[i] = pack16(r[i + 16], r[i]);           // F init = U0 (packed)

    // 999 chained iterations: U = hmac(pw, U); Fp ^= packed(U).
    // Absorb collapse: r[j] = c[j] + r[16+j] (9-bit OK, mix LOP3 re-masks),
    // r[16+j] = old r[j] (order-2 swap; even unroll -> pure renaming).
    #pragma unroll 4
    for (int it = 1; it < 1000; it++) {
        #pragma unroll
        for (int j = 0; j < 16; j++) {
            unsigned t = r[j];
            r[j] = c[j] + r[16 + j];
            r[16 + j] = t;
        }
        #pragma unroll
        for (int rd = 0; rd < 3; rd++) {
            #pragma unroll
            for (int i = 0; i < 32; i++)
                r[i] = (r[i] ^ (r[(i + 17) & 31] + r[(i + 11) & 31])) & 255u;
        }
        // round 4: steps 0..15 plain; steps 16..31 fused with packed F-xor
        #pragma unroll
        for (int i = 0; i < 16; i++)
            r[i] = (r[i] ^ (r[(i + 17) & 31] + r[(i + 11) & 31])) & 255u;
        #pragma unroll
        for (int i = 16; i < 32; i++) {
            r[i] = (r[i] ^ (r[(i + 17) & 31] + r[(i + 11) & 31])) & 255u;
            Fp[i - 16] ^= pack16(r[i], r[i - 16]);  // IMAD (fma) + LOP3 (alu)
        }
    }

    if (threadIdx.x == 0) {
        #pragma unroll
        for (int i = 0; i < 16; i++) {
            out[i]      = (float)(Fp[i] & 0xFFFFu);
            out[i + 16] = (float)(Fp[i] >> 16);
        }
    }
}

extern "C" void kernel_launch(void* const* d_in, const int* in_sizes, int n_in,
                              void* d_out, int out_size) {
    const void* password = d_in[0];
    const void* salt     = (n_in >= 2) ? d_in[1] : (const void*)((const int*)d_in[0] + 16);
    float* out           = (float*)d_out;
    Model_62955630625117_kernel<<<1, 32>>>(password, salt, out);
}